// round 7
// baseline (speedup 1.0000x reference)
#include <cuda_runtime.h>
#include <math.h>

#define BB 8
#define TT 4096
#define EE 64
#define DD 8
#define TILE 256
#define RPW 4
#define WARPS 8
#define ROWS_PER_GROUP (RPW*WARPS)           /* 32 */
#define GROUPS_PER_BATCH (TT/ROWS_PER_GROUP) /* 128 */
#define NUNITS (BB*GROUPS_PER_BATCH)         /* 1024 */
#define GRID_ATTN 304

typedef unsigned long long u64;

__device__ __forceinline__ u64 fmul2(u64 a, u64 b){ u64 d; asm("mul.rn.f32x2 %0,%1,%2;":"=l"(d):"l"(a),"l"(b)); return d; }
__device__ __forceinline__ u64 ffma2(u64 a, u64 b, u64 c){ u64 d; asm("fma.rn.f32x2 %0,%1,%2,%3;":"=l"(d):"l"(a),"l"(b),"l"(c)); return d; }
__device__ __forceinline__ void unpack2(u64 a, float& l, float& h){ asm("mov.b64 {%0,%1},%2;":"=f"(l),"=f"(h):"l"(a)); }
__device__ __forceinline__ u64 pack2(float l, float h){ u64 d; asm("mov.b64 %0,{%1,%2};":"=l"(d):"f"(l),"f"(h)); return d; }
__device__ __forceinline__ float ex2f(float x){ float r; asm("ex2.approx.f32 %0,%1;":"=f"(r):"f"(x)); return r; }

// scratch (no allocations allowed)
__device__ __align__(16) float g_q[BB*TT*DD];
__device__ __align__(16) float g_kt[BB*TT*DD];   // kt[b][t2][i] = reshaped-K column layout
__device__ __align__(16) float g_v[BB*TT*DD];
__device__ int g_ctr;                            // work-unit counter (reset by proj)

// -------------------- projection: q, kt, v from x --------------------
__global__ __launch_bounds__(256) void proj_kernel(
    const float* __restrict__ x,
    const float* __restrict__ Wq, const float* __restrict__ bq,
    const float* __restrict__ Wk, const float* __restrict__ bk,
    const float* __restrict__ Wv, const float* __restrict__ bv)
{
    if (blockIdx.x == 0 && threadIdx.x == 0) g_ctr = 0;  // reset scheduler

    __shared__ __align__(16) float sW[3][EE][DD];
    __shared__ float sb[3][DD];
    int tid = threadIdx.x;
    for (int i = tid; i < EE*DD; i += 256) {
        sW[0][i>>3][i&7] = Wq[i];
        sW[1][i>>3][i&7] = Wk[i];
        sW[2][i>>3][i&7] = Wv[i];
    }
    if (tid < DD) { sb[0][tid]=bq[tid]; sb[1][tid]=bk[tid]; sb[2][tid]=bv[tid]; }
    __syncthreads();

    int row = blockIdx.x*256 + tid;       // 0 .. B*T-1
    int b = row >> 12;
    int t = row & (TT-1);

    float aq[8], ak[8], av[8];
    #pragma unroll
    for (int i=0;i<8;i++){ aq[i]=sb[0][i]; ak[i]=sb[1][i]; av[i]=sb[2][i]; }

    const float4* xr = (const float4*)(x + (size_t)row*EE);
    #pragma unroll
    for (int j4 = 0; j4 < 16; j4++) {
        float4 xv = xr[j4];
        float xs[4] = {xv.x, xv.y, xv.z, xv.w};
        #pragma unroll
        for (int m = 0; m < 4; m++) {
            int jj = j4*4 + m;
            float xsm = xs[m];
            #pragma unroll
            for (int i = 0; i < 8; i++) {
                aq[i] = fmaf(xsm, sW[0][jj][i], aq[i]);
                ak[i] = fmaf(xsm, sW[1][jj][i], ak[i]);
                av[i] = fmaf(xsm, sW[2][jj][i], av[i]);
            }
        }
    }

    float4* qo = (float4*)(g_q + (size_t)row*8);
    qo[0] = make_float4(aq[0],aq[1],aq[2],aq[3]);
    qo[1] = make_float4(aq[4],aq[5],aq[6],aq[7]);
    float4* vo = (float4*)(g_v + (size_t)row*8);
    vo[0] = make_float4(av[0],av[1],av[2],av[3]);
    vo[1] = make_float4(av[4],av[5],av[6],av[7]);

    // reshape scatter: flat idx t*8+c -> i = t>>9, j = (t&511)*8+c
    int ich = t >> 9;
    int j0  = (t & 511) * 8;
    float* kb = g_kt + (size_t)b*TT*8;
    #pragma unroll
    for (int c = 0; c < 8; c++)
        kb[(size_t)(j0 + c)*8 + ich] = ak[c];
}

// -------------------- attention --------------------
// Persistent blocks self-schedule single row-groups (32 rows) in descending-g
// (LPT) order via a global atomic counter: no wave-quantization tail, near-
// perfect triangular load balance. 8 warps/block, 4 rows/warp.
// smem tile: TILE columns, 20 floats each (kt[8], v[8], 4 pad); 80B stride is
// conflict-free for 128-bit LDS phases.
// Math: f32x2 dot (q pre-scaled by (1/sqrt8)*log2e -> bare ex2), scalar-FFMA
// accumulate (no pack MOVs). No w==0 checks: upper triangle is handled by the
// causal compare; an exact fp32 zero in the kept region is measure-zero.
__global__ __launch_bounds__(256) void attn_kernel(float* __restrict__ out)
{
    __shared__ __align__(16) float sm[TILE*20];
    __shared__ int s_u;

    const int tid  = threadIdx.x;
    const int lane = tid & 31;
    const int w    = tid >> 5;

    const float CSCALE = 0.35355339059327373f * 1.4426950408889634f;

    for (;;) {
        __syncthreads();   // protect s_u from previous iteration's readers
        if (tid == 0) s_u = atomicAdd(&g_ctr, 1);
        __syncthreads();
        const int u = s_u;
        if (u >= NUNITS) return;

        const int b = u & (BB-1);
        const int g = (GROUPS_PER_BATCH-1) - (u >> 3);   // descending size

        const float* qb  = g_q  + (size_t)b*TT*8;
        const float* ktb = g_kt + (size_t)b*TT*8;
        const float* vb  = g_v  + (size_t)b*TT*8;
        float*       ob  = out  + (size_t)b*TT*8;

        const int r0 = g*ROWS_PER_GROUP + w*RPW;

        u64 q2[RPW][4];
        #pragma unroll
        for (int r = 0; r < RPW; r++) {
            const float* qr = qb + (size_t)(r0+r)*8;
            float4 a = *(const float4*)(qr);
            float4 c = *(const float4*)(qr + 4);
            q2[r][0] = pack2(a.x*CSCALE, a.y*CSCALE);
            q2[r][1] = pack2(a.z*CSCALE, a.w*CSCALE);
            q2[r][2] = pack2(c.x*CSCALE, c.y*CSCALE);
            q2[r][3] = pack2(c.z*CSCALE, c.w*CSCALE);
        }

        float acc[RPW][8];
        float lsum[RPW];
        #pragma unroll
        for (int r = 0; r < RPW; r++) {
            lsum[r] = 0.f;
            #pragma unroll
            for (int i = 0; i < 8; i++) acc[r][i] = 0.f;
        }

        const int maxrow = g*ROWS_PER_GROUP + ROWS_PER_GROUP - 1;
        const int ntiles = maxrow / TILE + 1;

        for (int ti = 0; ti < ntiles; ti++) {
            const int tbase = ti * TILE;
            __syncthreads();
            // cooperative tile load: 256 cols x 4 float4-chunks
            #pragma unroll
            for (int kk = 0; kk < 4; kk++) {
                int chunk = tid + kk*256;
                int col  = chunk >> 2;
                int part = chunk & 3;
                const float* src = (part < 2 ? ktb : vb)
                                   + (size_t)(tbase + col)*8 + (part & 1)*4;
                *(float4*)&sm[col*20 + part*4] = *(const float4*)src;
            }
            __syncthreads();

            if (tbase + TILE - 1 <= r0) {
                // fully unmasked tile: zero selects, zero compares
                #pragma unroll 2
                for (int it = 0; it < TILE/32; it++) {
                    const float* cp = &sm[(it*32 + lane)*20];
                    ulonglong2 ka  = *(const ulonglong2*)(cp);
                    ulonglong2 kb2 = *(const ulonglong2*)(cp + 4);
                    float p[RPW];
                    #pragma unroll
                    for (int r = 0; r < RPW; r++) {
                        u64 d2 = fmul2(q2[r][0], ka.x);
                        d2 = ffma2(q2[r][1], ka.y, d2);
                        d2 = ffma2(q2[r][2], kb2.x, d2);
                        d2 = ffma2(q2[r][3], kb2.y, d2);
                        float tl, th; unpack2(d2, tl, th);
                        p[r] = ex2f(tl + th);
                    }
                    float4 v0 = *(const float4*)(cp + 8);
                    float4 v1 = *(const float4*)(cp + 12);
                    #pragma unroll
                    for (int r = 0; r < RPW; r++) {
                        float pr = p[r];
                        lsum[r] += pr;
                        acc[r][0] = fmaf(pr, v0.x, acc[r][0]);
                        acc[r][1] = fmaf(pr, v0.y, acc[r][1]);
                        acc[r][2] = fmaf(pr, v0.z, acc[r][2]);
                        acc[r][3] = fmaf(pr, v0.w, acc[r][3]);
                        acc[r][4] = fmaf(pr, v1.x, acc[r][4]);
                        acc[r][5] = fmaf(pr, v1.y, acc[r][5]);
                        acc[r][6] = fmaf(pr, v1.z, acc[r][6]);
                        acc[r][7] = fmaf(pr, v1.w, acc[r][7]);
                    }
                }
            } else {
                // boundary tile: per-row causal guard only
                #pragma unroll 2
                for (int it = 0; it < TILE/32; it++) {
                    const int t2 = tbase + it*32 + lane;
                    const float* cp = &sm[(it*32 + lane)*20];
                    ulonglong2 ka  = *(const ulonglong2*)(cp);
                    ulonglong2 kb2 = *(const ulonglong2*)(cp + 4);
                    float p[RPW];
                    #pragma unroll
                    for (int r = 0; r < RPW; r++) {
                        u64 d2 = fmul2(q2[r][0], ka.x);
                        d2 = ffma2(q2[r][1], ka.y, d2);
                        d2 = ffma2(q2[r][2], kb2.x, d2);
                        d2 = ffma2(q2[r][3], kb2.y, d2);
                        float tl, th; unpack2(d2, tl, th);
                        float pr = ex2f(tl + th);
                        p[r] = (t2 <= r0 + r) ? pr : 0.f;
                    }
                    float4 v0 = *(const float4*)(cp + 8);
                    float4 v1 = *(const float4*)(cp + 12);
                    #pragma unroll
                    for (int r = 0; r < RPW; r++) {
                        float pr = p[r];
                        lsum[r] += pr;
                        acc[r][0] = fmaf(pr, v0.x, acc[r][0]);
                        acc[r][1] = fmaf(pr, v0.y, acc[r][1]);
                        acc[r][2] = fmaf(pr, v0.z, acc[r][2]);
                        acc[r][3] = fmaf(pr, v0.w, acc[r][3]);
                        acc[r][4] = fmaf(pr, v1.x, acc[r][4]);
                        acc[r][5] = fmaf(pr, v1.y, acc[r][5]);
                        acc[r][6] = fmaf(pr, v1.z, acc[r][6]);
                        acc[r][7] = fmaf(pr, v1.w, acc[r][7]);
                    }
                }
            }
        }

        // epilogue: warp-reduce (l, acc[8]) per row, lane 0 writes
        #pragma unroll
        for (int r = 0; r < RPW; r++) {
            float vals[9];
            #pragma unroll
            for (int i = 0; i < 8; i++) vals[i] = acc[r][i];
            vals[8] = lsum[r];
            #pragma unroll
            for (int i = 0; i < 9; i++) {
                #pragma unroll
                for (int o = 16; o > 0; o >>= 1)
                    vals[i] += __shfl_xor_sync(0xffffffffu, vals[i], o);
            }
            if (lane == 0) {
                float inv = 1.f / vals[8];
                float4 o0 = make_float4(vals[0]*inv, vals[1]*inv, vals[2]*inv, vals[3]*inv);
                float4 o1 = make_float4(vals[4]*inv, vals[5]*inv, vals[6]*inv, vals[7]*inv);
                *(float4*)(ob + (size_t)(r0+r)*8)     = o0;
                *(float4*)(ob + (size_t)(r0+r)*8 + 4) = o1;
            }
        }
    }
}

extern "C" void kernel_launch(void* const* d_in, const int* in_sizes, int n_in,
                              void* d_out, int out_size)
{
    (void)in_sizes; (void)n_in; (void)out_size;
    const float* x  = (const float*)d_in[0];
    const float* Wq = (const float*)d_in[1];
    const float* bq = (const float*)d_in[2];
    const float* Wk = (const float*)d_in[3];
    const float* bk = (const float*)d_in[4];
    const float* Wv = (const float*)d_in[5];
    const float* bv = (const float*)d_in[6];
    float* out = (float*)d_out;

    proj_kernel<<<(BB*TT)/256, 256>>>(x, Wq, bq, Wk, bk, Wv, bv);
    attn_kernel<<<GRID_ATTN, 256>>>(out);
}

// round 9
// speedup vs baseline: 1.5738x; 1.5738x over previous
#include <cuda_runtime.h>
#include <math.h>

#define BB 8
#define TT 4096
#define EE 64
#define DD 8
#define TILE 256
#define RPW 8
#define WARPS 8
#define ROWS_PER_GROUP (RPW*WARPS)           /* 64 */
#define GROUPS_PER_BATCH (TT/ROWS_PER_GROUP) /* 64 */
#define NUNITS (BB*GROUPS_PER_BATCH)         /* 512 */
#define GRID_ATTN 152

typedef unsigned long long u64;

__device__ __forceinline__ u64 fmul2(u64 a, u64 b){ u64 d; asm("mul.rn.f32x2 %0,%1,%2;":"=l"(d):"l"(a),"l"(b)); return d; }
__device__ __forceinline__ u64 ffma2(u64 a, u64 b, u64 c){ u64 d; asm("fma.rn.f32x2 %0,%1,%2,%3;":"=l"(d):"l"(a),"l"(b),"l"(c)); return d; }
__device__ __forceinline__ void unpack2(u64 a, float& l, float& h){ asm("mov.b64 {%0,%1},%2;":"=f"(l),"=f"(h):"l"(a)); }
__device__ __forceinline__ u64 pack2(float l, float h){ u64 d; asm("mov.b64 %0,{%1,%2};":"=l"(d):"f"(l),"f"(h)); return d; }
__device__ __forceinline__ float ex2f(float x){ float r; asm("ex2.approx.f32 %0,%1;":"=f"(r):"f"(x)); return r; }

__device__ __forceinline__ void cpasync16(float* dst, const float* src){
    unsigned s = (unsigned)__cvta_generic_to_shared(dst);
    asm volatile("cp.async.cg.shared.global [%0], [%1], 16;" :: "r"(s), "l"(src));
}
__device__ __forceinline__ void cpcommit(){ asm volatile("cp.async.commit_group;"); }
__device__ __forceinline__ void cpwait1(){ asm volatile("cp.async.wait_group 1;"); }
__device__ __forceinline__ void cpwait0(){ asm volatile("cp.async.wait_group 0;"); }

// scratch (no allocations allowed)
__device__ __align__(16) float g_q[BB*TT*DD];
__device__ __align__(16) float g_kt[BB*TT*DD];   // kt[b][t2][i] = reshaped-K column layout
__device__ __align__(16) float g_v[BB*TT*DD];
__device__ int g_ctr;                            // work-unit counter (reset by proj)

// -------------------- projection: q, kt, v from x --------------------
__global__ __launch_bounds__(256) void proj_kernel(
    const float* __restrict__ x,
    const float* __restrict__ Wq, const float* __restrict__ bq,
    const float* __restrict__ Wk, const float* __restrict__ bk,
    const float* __restrict__ Wv, const float* __restrict__ bv)
{
    if (blockIdx.x == 0 && threadIdx.x == 0) g_ctr = 0;  // reset scheduler

    __shared__ __align__(16) float sW[3][EE][DD];
    __shared__ float sb[3][DD];
    int tid = threadIdx.x;
    for (int i = tid; i < EE*DD; i += 256) {
        sW[0][i>>3][i&7] = Wq[i];
        sW[1][i>>3][i&7] = Wk[i];
        sW[2][i>>3][i&7] = Wv[i];
    }
    if (tid < DD) { sb[0][tid]=bq[tid]; sb[1][tid]=bk[tid]; sb[2][tid]=bv[tid]; }
    __syncthreads();

    int row = blockIdx.x*256 + tid;       // 0 .. B*T-1
    int b = row >> 12;
    int t = row & (TT-1);

    float aq[8], ak[8], av[8];
    #pragma unroll
    for (int i=0;i<8;i++){ aq[i]=sb[0][i]; ak[i]=sb[1][i]; av[i]=sb[2][i]; }

    const float4* xr = (const float4*)(x + (size_t)row*EE);
    #pragma unroll
    for (int j4 = 0; j4 < 16; j4++) {
        float4 xv = xr[j4];
        float xs[4] = {xv.x, xv.y, xv.z, xv.w};
        #pragma unroll
        for (int m = 0; m < 4; m++) {
            int jj = j4*4 + m;
            float xsm = xs[m];
            #pragma unroll
            for (int i = 0; i < 8; i++) {
                aq[i] = fmaf(xsm, sW[0][jj][i], aq[i]);
                ak[i] = fmaf(xsm, sW[1][jj][i], ak[i]);
                av[i] = fmaf(xsm, sW[2][jj][i], av[i]);
            }
        }
    }

    float4* qo = (float4*)(g_q + (size_t)row*8);
    qo[0] = make_float4(aq[0],aq[1],aq[2],aq[3]);
    qo[1] = make_float4(aq[4],aq[5],aq[6],aq[7]);
    float4* vo = (float4*)(g_v + (size_t)row*8);
    vo[0] = make_float4(av[0],av[1],av[2],av[3]);
    vo[1] = make_float4(av[4],av[5],av[6],av[7]);

    // reshape scatter: flat idx t*8+c -> i = t>>9, j = (t&511)*8+c
    int ich = t >> 9;
    int j0  = (t & 511) * 8;
    float* kb = g_kt + (size_t)b*TT*8;
    #pragma unroll
    for (int c = 0; c < 8; c++)
        kb[(size_t)(j0 + c)*8 + ich] = ak[c];
}

// -------------------- attention --------------------
// Persistent blocks pop 64-row groups (8 warps x 8 rows) LPT-descending from a
// global counter. Tiles of 256 columns are double-buffered via cp.async so the
// gmem->smem latency overlaps compute. Each column's 64B (kt+v) is reused by 8
// rows -> 8B LDS per element. Dot + accumulate in packed f32x2 (10 fma-pipe
// instrs / element); q pre-scaled by (1/sqrt8)*log2e so exp is a bare ex2;
// masking is the integer causal compare only (boundary tiles).
__global__ __launch_bounds__(256, 1) void attn_kernel(float* __restrict__ out)
{
    __shared__ __align__(16) float sm[2][TILE*20];
    __shared__ int s_u;

    const int tid  = threadIdx.x;
    const int lane = tid & 31;
    const int w    = tid >> 5;

    // per-thread cooperative-load coordinates (4 x 16B chunks per tile)
    int l_col[4], l_part[4];
    #pragma unroll
    for (int kk = 0; kk < 4; kk++) {
        int chunk = tid + kk*256;
        l_col[kk]  = chunk >> 2;
        l_part[kk] = chunk & 3;
    }

    const float CSCALE = 0.35355339059327373f * 1.4426950408889634f;

    for (;;) {
        __syncthreads();   // protect s_u from previous iteration's readers
        if (tid == 0) s_u = atomicAdd(&g_ctr, 1);
        __syncthreads();
        const int u = s_u;
        if (u >= NUNITS) return;

        const int b = u & (BB-1);
        const int g = (GROUPS_PER_BATCH-1) - (u >> 3);   // descending size (LPT)

        const float* qb  = g_q  + (size_t)b*TT*8;
        const float* ktb = g_kt + (size_t)b*TT*8;
        const float* vb  = g_v  + (size_t)b*TT*8;
        float*       ob  = out  + (size_t)b*TT*8;

        const int r0 = g*ROWS_PER_GROUP + w*RPW;

        u64 q2[RPW][4];
        #pragma unroll
        for (int r = 0; r < RPW; r++) {
            const float* qr = qb + (size_t)(r0+r)*8;
            float4 a = *(const float4*)(qr);
            float4 c = *(const float4*)(qr + 4);
            q2[r][0] = pack2(a.x*CSCALE, a.y*CSCALE);
            q2[r][1] = pack2(a.z*CSCALE, a.w*CSCALE);
            q2[r][2] = pack2(c.x*CSCALE, c.y*CSCALE);
            q2[r][3] = pack2(c.z*CSCALE, c.w*CSCALE);
        }

        u64 acc2[RPW][4];
        float lsum[RPW];
        #pragma unroll
        for (int r = 0; r < RPW; r++) {
            lsum[r] = 0.f;
            #pragma unroll
            for (int i = 0; i < 4; i++) acc2[r][i] = 0ull;
        }

        const int ntiles = (g*ROWS_PER_GROUP + ROWS_PER_GROUP - 1) / TILE + 1;

        // prologue: async-load tile 0 into buffer 0
        #pragma unroll
        for (int kk = 0; kk < 4; kk++) {
            const float* src = (l_part[kk] < 2 ? ktb : vb)
                               + (size_t)l_col[kk]*8 + (l_part[kk] & 1)*4;
            cpasync16(&sm[0][l_col[kk]*20 + l_part[kk]*4], src);
        }
        cpcommit();

        for (int ti = 0; ti < ntiles; ti++) {
            const int tbase = ti * TILE;
            // prefetch next tile into the other buffer, then wait for current
            if (ti + 1 < ntiles) {
                const int nb = tbase + TILE;
                #pragma unroll
                for (int kk = 0; kk < 4; kk++) {
                    const float* src = (l_part[kk] < 2 ? ktb : vb)
                                       + (size_t)(nb + l_col[kk])*8 + (l_part[kk] & 1)*4;
                    cpasync16(&sm[(ti+1)&1][l_col[kk]*20 + l_part[kk]*4], src);
                }
                cpcommit();
                cpwait1();
            } else {
                cpwait0();
            }
            __syncthreads();   // current buffer visible to all
            const float* buf = sm[ti & 1];

            if (tbase + TILE - 1 <= r0) {
                // fully unmasked tile
                #pragma unroll 2
                for (int it = 0; it < TILE/32; it++) {
                    const float* cp = buf + (it*32 + lane)*20;
                    ulonglong2 ka  = *(const ulonglong2*)(cp);
                    ulonglong2 kb2 = *(const ulonglong2*)(cp + 4);
                    float p[RPW];
                    #pragma unroll
                    for (int r = 0; r < RPW; r++) {
                        u64 d2 = fmul2(q2[r][0], ka.x);
                        d2 = ffma2(q2[r][1], ka.y, d2);
                        d2 = ffma2(q2[r][2], kb2.x, d2);
                        d2 = ffma2(q2[r][3], kb2.y, d2);
                        float tl, th; unpack2(d2, tl, th);
                        p[r] = ex2f(tl + th);
                    }
                    ulonglong2 va  = *(const ulonglong2*)(cp + 8);
                    ulonglong2 vb2 = *(const ulonglong2*)(cp + 12);
                    #pragma unroll
                    for (int r = 0; r < RPW; r++) {
                        float pr = p[r];
                        lsum[r] += pr;
                        u64 p2 = pack2(pr, pr);
                        acc2[r][0] = ffma2(p2, va.x,  acc2[r][0]);
                        acc2[r][1] = ffma2(p2, va.y,  acc2[r][1]);
                        acc2[r][2] = ffma2(p2, vb2.x, acc2[r][2]);
                        acc2[r][3] = ffma2(p2, vb2.y, acc2[r][3]);
                    }
                }
            } else {
                // boundary tile: per-row causal guard only
                #pragma unroll 2
                for (int it = 0; it < TILE/32; it++) {
                    const int t2 = tbase + it*32 + lane;
                    const float* cp = buf + (it*32 + lane)*20;
                    ulonglong2 ka  = *(const ulonglong2*)(cp);
                    ulonglong2 kb2 = *(const ulonglong2*)(cp + 4);
                    float p[RPW];
                    #pragma unroll
                    for (int r = 0; r < RPW; r++) {
                        u64 d2 = fmul2(q2[r][0], ka.x);
                        d2 = ffma2(q2[r][1], ka.y, d2);
                        d2 = ffma2(q2[r][2], kb2.x, d2);
                        d2 = ffma2(q2[r][3], kb2.y, d2);
                        float tl, th; unpack2(d2, tl, th);
                        float pr = ex2f(tl + th);
                        p[r] = (t2 <= r0 + r) ? pr : 0.f;
                    }
                    ulonglong2 va  = *(const ulonglong2*)(cp + 8);
                    ulonglong2 vb2 = *(const ulonglong2*)(cp + 12);
                    #pragma unroll
                    for (int r = 0; r < RPW; r++) {
                        float pr = p[r];
                        lsum[r] += pr;
                        u64 p2 = pack2(pr, pr);
                        acc2[r][0] = ffma2(p2, va.x,  acc2[r][0]);
                        acc2[r][1] = ffma2(p2, va.y,  acc2[r][1]);
                        acc2[r][2] = ffma2(p2, vb2.x, acc2[r][2]);
                        acc2[r][3] = ffma2(p2, vb2.y, acc2[r][3]);
                    }
                }
            }
            __syncthreads();   // everyone done reading buf before it is refilled
        }

        // epilogue: warp-reduce (l, acc[8]) per row, lane 0 writes
        #pragma unroll
        for (int r = 0; r < RPW; r++) {
            float vals[9];
            #pragma unroll
            for (int i = 0; i < 4; i++) unpack2(acc2[r][i], vals[2*i], vals[2*i+1]);
            vals[8] = lsum[r];
            #pragma unroll
            for (int i = 0; i < 9; i++) {
                #pragma unroll
                for (int o = 16; o > 0; o >>= 1)
                    vals[i] += __shfl_xor_sync(0xffffffffu, vals[i], o);
            }
            if (lane == 0) {
                float inv = 1.f / vals[8];
                float4 o0 = make_float4(vals[0]*inv, vals[1]*inv, vals[2]*inv, vals[3]*inv);
                float4 o1 = make_float4(vals[4]*inv, vals[5]*inv, vals[6]*inv, vals[7]*inv);
                *(float4*)(ob + (size_t)(r0+r)*8)     = o0;
                *(float4*)(ob + (size_t)(r0+r)*8 + 4) = o1;
            }
        }
    }
}

extern "C" void kernel_launch(void* const* d_in, const int* in_sizes, int n_in,
                              void* d_out, int out_size)
{
    (void)in_sizes; (void)n_in; (void)out_size;
    const float* x  = (const float*)d_in[0];
    const float* Wq = (const float*)d_in[1];
    const float* bq = (const float*)d_in[2];
    const float* Wk = (const float*)d_in[3];
    const float* bk = (const float*)d_in[4];
    const float* Wv = (const float*)d_in[5];
    const float* bv = (const float*)d_in[6];
    float* out = (float*)d_out;

    proj_kernel<<<(BB*TT)/256, 256>>>(x, Wq, bq, Wk, bk, Wv, bv);
    attn_kernel<<<GRID_ATTN, 256>>>(out);
}